// round 13
// baseline (speedup 1.0000x reference)
#include <cuda_runtime.h>
#include <cuda_bf16.h>
#include <cstdint>
#include <cstddef>

// Problem dims (fixed by the dataset)
#define M_TOTAL 8192
#define K_DIM   4096
#define N_DIM   16384
#define TILE_M  128
#define TILE_N  128
#define TILE_K  64
#define K_ITERS (K_DIM / TILE_K)   // 64
#define N_TILES (N_DIM / TILE_N)   // 128
#define M_TILES (M_TOTAL / TILE_M) // 64
#define THREADS 256                // 8 warps: 4(M) x 2(N), 32x64 per warp
#define STAGES  3
#define KSLICES (K_DIM / 32)       // 128 norm partials

#define A_STAGE (TILE_M * TILE_K * 2)            // 16384 B
#define B_STAGE (TILE_N * TILE_K * 2)            // 16384 B
#define STAGE_BYTES (A_STAGE + B_STAGE)          // 32768
#define RED_BYTES  (2 * TILE_M * 8)              // 2048 (dedicated reduction buffer)
#define SMEM_TOTAL_GEMM (STAGES * STAGE_BYTES + RED_BYTES)   // 100352 (x2 CTAs fits 228K)

#define WT_BLOCKS ((N_DIM / 32) * (K_DIM / 32))  // 65536
#define GB_BLOCKS ((M_TOTAL * K_DIM / 4) / 256)  // 32768

// -------- static device scratch (no allocations allowed) --------
__device__ float          d_norm_part[(size_t)KSLICES * N_DIM];   // per-k-slice col sq-sums
__device__ float          d_norm_inv[N_DIM];
__device__ __nv_bfloat16  d_gb[(size_t)M_TOTAL * K_DIM];          // g in bf16, [M,K] row-major
__device__ __nv_bfloat16  d_wt[(size_t)N_DIM * K_DIM];            // W^T bf16 (UNnormalized), [N,K]
__device__ float          d_partial[(size_t)N_TILES * M_TOTAL];   // partial LSE [n_tile][m]

// ------------------------- PTX helpers -------------------------
__device__ __forceinline__ uint32_t smem_u32(const void* p) {
    return (uint32_t)__cvta_generic_to_shared(p);
}
__device__ __forceinline__ void cp_async16(uint32_t smem, const void* gmem) {
    asm volatile("cp.async.cg.shared.global [%0], [%1], 16;" :: "r"(smem), "l"(gmem));
}
__device__ __forceinline__ void cp_commit() {
    asm volatile("cp.async.commit_group;" ::: "memory");
}
__device__ __forceinline__ void cp_wait1() {
    asm volatile("cp.async.wait_group 1;" ::: "memory");
}
__device__ __forceinline__ void ldsm_x4(uint32_t& r0, uint32_t& r1, uint32_t& r2, uint32_t& r3,
                                        uint32_t addr) {
    asm volatile("ldmatrix.sync.aligned.m8n8.x4.shared.b16 {%0,%1,%2,%3}, [%4];"
                 : "=r"(r0), "=r"(r1), "=r"(r2), "=r"(r3) : "r"(addr));
}
__device__ __forceinline__ void mma_bf16(float& d0, float& d1, float& d2, float& d3,
                                         uint32_t a0, uint32_t a1, uint32_t a2, uint32_t a3,
                                         uint32_t b0, uint32_t b1) {
    asm volatile(
        "mma.sync.aligned.m16n8k16.row.col.f32.bf16.bf16.f32 "
        "{%0,%1,%2,%3}, {%4,%5,%6,%7}, {%8,%9}, {%0,%1,%2,%3};"
        : "+f"(d0), "+f"(d1), "+f"(d2), "+f"(d3)
        : "r"(a0), "r"(a1), "r"(a2), "r"(a3), "r"(b0), "r"(b1));
}
__device__ __forceinline__ uint32_t swz(uint32_t byte_off) {
    return byte_off ^ ((byte_off >> 3) & 0x70);
}

// --------------------- merged prep kernel ---------------------
// Blocks [0, WT_BLOCKS): transpose W -> bf16 (unnormalized) + per-k-slice
// column sq-sums. Blocks [WT_BLOCKS, WT_BLOCKS+GB_BLOCKS): g -> bf16.
// Both are DRAM-bound; merging overlaps their memory streams.
__global__ void prep_kernel(const float* __restrict__ W, const float4* __restrict__ g) {
    __shared__ float tile[32][33];     // [k_local][h_local] (wt path only)
    const int b = blockIdx.x;
    const int tid = threadIdx.x;

    if (b < WT_BLOCKS) {
        const int h0 = (b & (N_DIM / 32 - 1)) * 32;
        const int kb = b >> 9;                       // k-slice index (N_DIM/32 = 512 = 2^9)
        const int k0 = kb * 32;
        const int tx = tid & 31, ty = tid >> 5;      // (32, 8)
#pragma unroll
        for (int j = 0; j < 32; j += 8)
            tile[ty + j][tx] = W[(size_t)(k0 + ty + j) * N_DIM + h0 + tx];
        __syncthreads();
#pragma unroll
        for (int j = 0; j < 32; j += 8) {
            int h = h0 + ty + j;
            d_wt[(size_t)h * K_DIM + k0 + tx] = __float2bfloat16(tile[tx][ty + j]);
        }
        const int hl = tid >> 3;                     // 0..31
        const int kc = tid & 7;                      // 0..7 (4 k each)
        float sq = 0.f;
#pragma unroll
        for (int i = 0; i < 4; ++i) {
            float v = tile[kc * 4 + i][hl];
            sq = fmaf(v, v, sq);
        }
        sq += __shfl_down_sync(0xFFFFFFFF, sq, 4);
        sq += __shfl_down_sync(0xFFFFFFFF, sq, 2);
        sq += __shfl_down_sync(0xFFFFFFFF, sq, 1);
        if (kc == 0)
            d_norm_part[(size_t)kb * N_DIM + h0 + hl] = sq;
    } else {
        int i = (b - WT_BLOCKS) * 256 + tid;
        float4 v = g[i];
        __nv_bfloat162* o = reinterpret_cast<__nv_bfloat162*>(d_gb) + (size_t)i * 2;
        o[0] = __floats2bfloat162_rn(v.x, v.y);
        o[1] = __floats2bfloat162_rn(v.z, v.w);
    }
}

// finalize: inv = rsqrt(sum of 128 partials)
__global__ void norm_finalize_kernel() {
    int h = blockIdx.x * blockDim.x + threadIdx.x;
    float s = 0.f;
#pragma unroll 8
    for (int p = 0; p < KSLICES; ++p) s += d_norm_part[(size_t)p * N_DIM + h];
    d_norm_inv[h] = rsqrtf(s);
}

// --------------------- persistent fused GEMM + partial LSE ---------------------
// grid = 2 * SM count; each CTA processes tiles t = bid + k*gridDim.x.
// The cp.async pipeline is CONTINUOUS across tiles: global iteration g,
// stage = g mod 3; tile t+1's first stages load during tile t's last
// iterations, and the epilogue (dedicated smem) overlaps the in-flight loads.

__global__ void __launch_bounds__(THREADS, 2) gemm_lse_kernel() {
    extern __shared__ char smem[];
    const uint32_t sb = smem_u32(smem);
    float2* red = (float2*)(smem + STAGES * STAGE_BYTES);   // dedicated, no stage alias
    const int tid = threadIdx.x;
    const int wid = tid >> 5;
    const int lane = tid & 31;
    const int mw = wid & 3;        // warp M index (0..3)
    const int nw = wid >> 2;       // warp N index (0..1)
    const int bid = blockIdx.x;
    const int grid = gridDim.x;

    const int totalTiles = M_TILES * N_TILES;               // 8192
    const int nT = (totalTiles - bid + grid - 1) / grid;
    if (nT <= 0) return;
    const int totalIters = nT * K_ITERS;

    // load global-iteration gg into stage s
    auto load_g = [&](int gg, int s) {
        const int lt = gg >> 6;
        const int it = gg & 63;
        const int t = bid + lt * grid;
        const char* aK = (const char*)d_gb
            + (size_t)((t & (M_TILES - 1)) * TILE_M) * (K_DIM * 2) + it * (TILE_K * 2);
        const char* bK = (const char*)d_wt
            + (size_t)((t >> 6) * TILE_N) * (K_DIM * 2) + it * (TILE_K * 2);
        const uint32_t ab = sb + s * STAGE_BYTES;
        const uint32_t bb = ab + A_STAGE;
#pragma unroll
        for (int i = 0; i < A_STAGE / 16 / THREADS; ++i) {        // 4
            int idx = tid + i * THREADS;
            cp_async16(ab + swz((uint32_t)idx * 16),
                       aK + (size_t)(idx >> 3) * (K_DIM * 2) + (idx & 7) * 16);
        }
#pragma unroll
        for (int i = 0; i < B_STAGE / 16 / THREADS; ++i) {        // 4
            int idx = tid + i * THREADS;
            cp_async16(bb + swz((uint32_t)idx * 16),
                       bK + (size_t)(idx >> 3) * (K_DIM * 2) + (idx & 7) * 16);
        }
    };

    load_g(0, 0); cp_commit();
    if (totalIters > 1) load_g(1, 1);
    cp_commit();

    // ---- precomputed swizzled LDSM offsets; k-chunk applied via XOR ----
    const int a_row = lane & 15;
    const int a_kh  = lane >> 4;
    const int b_row = lane & 7;
    const int b_grp = (lane >> 3) & 1;
    const int b_t2  = lane >> 4;
    uint32_t a_off[2], b_off[4];
#pragma unroll
    for (int t = 0; t < 2; ++t)
        a_off[t] = swz((uint32_t)(mw * 32 + t * 16 + a_row) * 128 + a_kh * 16);
#pragma unroll
    for (int p = 0; p < 4; ++p)
        b_off[p] = swz((uint32_t)(nw * 64 + p * 16 + b_t2 * 8 + b_row) * 128 + b_grp * 16);

    int g = 0;
    int sCur = 0, sLoad = 2;       // stage of current iter / of load target g+2

    for (int lt = 0; lt < nT; ++lt) {
        const int t = bid + lt * grid;
        const int m0 = (t & (M_TILES - 1)) * TILE_M;
        const int n0 = (t >> 6) * TILE_N;

        float acc[2][8][4];
#pragma unroll
        for (int tt = 0; tt < 2; ++tt)
#pragma unroll
            for (int j = 0; j < 8; ++j)
#pragma unroll
                for (int c = 0; c < 4; ++c) acc[tt][j][c] = 0.f;

        for (int it = 0; it < K_ITERS; ++it, ++g) {
            cp_wait1();                 // iteration g's stage complete
            __syncthreads();
            if (g + 2 < totalIters) load_g(g + 2, sLoad);
            cp_commit();

            const uint32_t stageA = sb + sCur * STAGE_BYTES;
            const uint32_t stageB = stageA + A_STAGE;

#pragma unroll
            for (int ks = 0; ks < TILE_K / 16; ++ks) {    // 4 k16 steps
                const uint32_t kx = (uint32_t)(ks * 32);
                uint32_t a[2][4];
#pragma unroll
                for (int tt = 0; tt < 2; ++tt)
                    ldsm_x4(a[tt][0], a[tt][1], a[tt][2], a[tt][3], stageA + (a_off[tt] ^ kx));
                uint32_t b[8][2];
#pragma unroll
                for (int p = 0; p < 4; ++p) {
                    uint32_t r0, r1, r2, r3;
                    ldsm_x4(r0, r1, r2, r3, stageB + (b_off[p] ^ kx));
                    b[p * 2][0] = r0; b[p * 2][1] = r1;
                    b[p * 2 + 1][0] = r2; b[p * 2 + 1][1] = r3;
                }
#pragma unroll
                for (int tt = 0; tt < 2; ++tt)
#pragma unroll
                    for (int j = 0; j < 8; ++j)
                        mma_bf16(acc[tt][j][0], acc[tt][j][1], acc[tt][j][2], acc[tt][j][3],
                                 a[tt][0], a[tt][1], a[tt][2], a[tt][3], b[j][0], b[j][1]);
            }
            if (++sCur == STAGES) sCur = 0;
            if (++sLoad == STAGES) sLoad = 0;
        }

        // ---- epilogue: normalize accumulators, partial LSE over 128 cols ----
        // (red is dedicated smem; next tile's loads may be in flight to stages)
        float ninv[8][2];
#pragma unroll
        for (int j = 0; j < 8; ++j) {
            int n = n0 + nw * 64 + j * 8 + (lane & 3) * 2;
            ninv[j][0] = d_norm_inv[n];
            ninv[j][1] = d_norm_inv[n + 1];
        }
#pragma unroll
        for (int tt = 0; tt < 2; ++tt)
#pragma unroll
            for (int j = 0; j < 8; ++j) {
                acc[tt][j][0] *= ninv[j][0];
                acc[tt][j][1] *= ninv[j][1];
                acc[tt][j][2] *= ninv[j][0];
                acc[tt][j][3] *= ninv[j][1];
            }

#pragma unroll
        for (int tt = 0; tt < 2; ++tt) {
#pragma unroll
            for (int half = 0; half < 2; ++half) {
                float mx = -3.4e38f;
#pragma unroll
                for (int j = 0; j < 8; ++j) {
                    mx = fmaxf(mx, acc[tt][j][half * 2]);
                    mx = fmaxf(mx, acc[tt][j][half * 2 + 1]);
                }
                mx = fmaxf(mx, __shfl_xor_sync(0xFFFFFFFF, mx, 1));
                mx = fmaxf(mx, __shfl_xor_sync(0xFFFFFFFF, mx, 2));
                float s = 0.f;
#pragma unroll
                for (int j = 0; j < 8; ++j) {
                    s += __expf(acc[tt][j][half * 2] - mx);
                    s += __expf(acc[tt][j][half * 2 + 1] - mx);
                }
                s += __shfl_xor_sync(0xFFFFFFFF, s, 1);
                s += __shfl_xor_sync(0xFFFFFFFF, s, 2);
                if ((lane & 3) == 0) {
                    int row = mw * 32 + tt * 16 + half * 8 + (lane >> 2);
                    red[nw * 128 + row] = make_float2(mx, s);
                }
            }
        }
        __syncthreads();
        if (tid < TILE_M) {
            float2 v0 = red[tid], v1 = red[128 + tid];
            float m = fmaxf(v0.x, v1.x);
            float s = v0.y * __expf(v0.x - m) + v1.y * __expf(v1.x - m);
            d_partial[(size_t)(t >> 6) * M_TOTAL + m0 + tid] = m + __logf(s);
        }
        __syncthreads();   // red reads done before next tile's writes
    }
}

// --------------------- final LSE combine ---------------------
__global__ void reduce_kernel(float* __restrict__ out) {
    int m = blockIdx.x * blockDim.x + threadIdx.x;
    if (m >= M_TOTAL) return;
    float mx = -3.4e38f;
#pragma unroll 8
    for (int j = 0; j < N_TILES; ++j)
        mx = fmaxf(mx, d_partial[(size_t)j * M_TOTAL + m]);
    float s = 0.f;
#pragma unroll 8
    for (int j = 0; j < N_TILES; ++j)
        s += __expf(d_partial[(size_t)j * M_TOTAL + m] - mx);
    out[m] = mx + logf(s);
}

// --------------------- launcher ---------------------
extern "C" void kernel_launch(void* const* d_in, const int* in_sizes, int n_in,
                              void* d_out, int out_size) {
    const float* g;
    const float* W;
    if (in_sizes[0] == M_TOTAL * K_DIM) {           // g first (expected metadata order)
        g = (const float*)d_in[0];
        W = (const float*)d_in[1];
    } else {
        g = (const float*)d_in[1];
        W = (const float*)d_in[0];
    }
    float* out = (float*)d_out;

    prep_kernel<<<WT_BLOCKS + GB_BLOCKS, 256>>>(W, (const float4*)g);
    norm_finalize_kernel<<<N_DIM / 256, 256>>>();

    int smCount = 148;
    cudaDeviceGetAttribute(&smCount, cudaDevAttrMultiProcessorCount, 0);
    int grid = smCount * 2;
    if (grid > M_TILES * N_TILES) grid = M_TILES * N_TILES;

    cudaFuncSetAttribute(gemm_lse_kernel, cudaFuncAttributeMaxDynamicSharedMemorySize,
                         SMEM_TOTAL_GEMM);
    gemm_lse_kernel<<<grid, THREADS, SMEM_TOTAL_GEMM>>>();

    reduce_kernel<<<(M_TOTAL + 255) / 256, 256>>>(out);
}

// round 14
// speedup vs baseline: 1.0584x; 1.0584x over previous
#include <cuda_runtime.h>
#include <cuda_bf16.h>
#include <cstdint>
#include <cstddef>

// Problem dims (fixed by the dataset)
#define M_TOTAL 8192
#define K_DIM   4096
#define N_DIM   16384
#define TILE_M  128
#define TILE_N  128
#define TILE_K  64
#define K_ITERS (K_DIM / TILE_K)   // 64
#define N_TILES (N_DIM / TILE_N)   // 128
#define M_TILES (M_TOTAL / TILE_M) // 64
#define THREADS 256                // 8 warps: 4(M) x 2(N), 32x64 per warp
#define STAGES  3
#define KSLICES (K_DIM / 32)       // 128 norm partials
#define JSPLIT  4                  // reduce parallelism over n_tiles

#define A_STAGE (TILE_M * TILE_K * 2)            // 16384 B
#define B_STAGE (TILE_N * TILE_K * 2)            // 16384 B
#define STAGE_BYTES (A_STAGE + B_STAGE)          // 32768
#define SMEM_TOTAL_GEMM (STAGES * STAGE_BYTES)   // 98304 (x2 CTAs = 192K/SM)

#define WT_BLOCKS ((N_DIM / 32) * (K_DIM / 32))  // 65536
#define GB_BLOCKS ((M_TOTAL * K_DIM / 4) / 256)  // 32768

// -------- static device scratch (no allocations allowed) --------
__device__ float          d_norm_part[(size_t)KSLICES * N_DIM];   // per-k-slice col sq-sums
__device__ float          d_norm_inv[N_DIM];
__device__ __nv_bfloat16  d_gb[(size_t)M_TOTAL * K_DIM];          // g in bf16, [M,K] row-major
__device__ __nv_bfloat16  d_wt[(size_t)N_DIM * K_DIM];            // W^T bf16 (UNnormalized), [N,K]
__device__ float          d_partial[(size_t)N_TILES * M_TOTAL];   // partial LSE [n_tile][m]
__device__ float2         d_partial2[(size_t)JSPLIT * M_TOTAL];   // stage-2 (max, sum) pairs

// ------------------------- PTX helpers -------------------------
__device__ __forceinline__ uint32_t smem_u32(const void* p) {
    return (uint32_t)__cvta_generic_to_shared(p);
}
__device__ __forceinline__ void cp_async16(uint32_t smem, const void* gmem) {
    asm volatile("cp.async.cg.shared.global [%0], [%1], 16;" :: "r"(smem), "l"(gmem));
}
__device__ __forceinline__ void cp_commit() {
    asm volatile("cp.async.commit_group;" ::: "memory");
}
__device__ __forceinline__ void cp_wait1() {
    asm volatile("cp.async.wait_group 1;" ::: "memory");
}
__device__ __forceinline__ void ldsm_x4(uint32_t& r0, uint32_t& r1, uint32_t& r2, uint32_t& r3,
                                        uint32_t addr) {
    asm volatile("ldmatrix.sync.aligned.m8n8.x4.shared.b16 {%0,%1,%2,%3}, [%4];"
                 : "=r"(r0), "=r"(r1), "=r"(r2), "=r"(r3) : "r"(addr));
}
__device__ __forceinline__ void mma_bf16(float& d0, float& d1, float& d2, float& d3,
                                         uint32_t a0, uint32_t a1, uint32_t a2, uint32_t a3,
                                         uint32_t b0, uint32_t b1) {
    asm volatile(
        "mma.sync.aligned.m16n8k16.row.col.f32.bf16.bf16.f32 "
        "{%0,%1,%2,%3}, {%4,%5,%6,%7}, {%8,%9}, {%0,%1,%2,%3};"
        : "+f"(d0), "+f"(d1), "+f"(d2), "+f"(d3)
        : "r"(a0), "r"(a1), "r"(a2), "r"(a3), "r"(b0), "r"(b1));
}
__device__ __forceinline__ uint32_t swz(uint32_t byte_off) {
    return byte_off ^ ((byte_off >> 3) & 0x70);
}

// --------------------- merged prep kernel ---------------------
// Blocks [0, WT_BLOCKS): transpose W -> bf16 (unnormalized) + per-k-slice
// column sq-sums. Blocks [WT_BLOCKS, ...): g -> bf16. Both DRAM-bound;
// merging overlaps their memory streams.
__global__ void prep_kernel(const float* __restrict__ W, const float4* __restrict__ g) {
    __shared__ float tile[32][33];     // [k_local][h_local] (wt path only)
    const int b = blockIdx.x;
    const int tid = threadIdx.x;

    if (b < WT_BLOCKS) {
        const int h0 = (b & (N_DIM / 32 - 1)) * 32;
        const int kb = b >> 9;                       // k-slice index (N_DIM/32 = 512)
        const int k0 = kb * 32;
        const int tx = tid & 31, ty = tid >> 5;      // (32, 8)
#pragma unroll
        for (int j = 0; j < 32; j += 8)
            tile[ty + j][tx] = W[(size_t)(k0 + ty + j) * N_DIM + h0 + tx];
        __syncthreads();
#pragma unroll
        for (int j = 0; j < 32; j += 8) {
            int h = h0 + ty + j;
            d_wt[(size_t)h * K_DIM + k0 + tx] = __float2bfloat16(tile[tx][ty + j]);
        }
        const int hl = tid >> 3;                     // 0..31
        const int kc = tid & 7;                      // 0..7 (4 k each)
        float sq = 0.f;
#pragma unroll
        for (int i = 0; i < 4; ++i) {
            float v = tile[kc * 4 + i][hl];
            sq = fmaf(v, v, sq);
        }
        sq += __shfl_down_sync(0xFFFFFFFF, sq, 4);
        sq += __shfl_down_sync(0xFFFFFFFF, sq, 2);
        sq += __shfl_down_sync(0xFFFFFFFF, sq, 1);
        if (kc == 0)
            d_norm_part[(size_t)kb * N_DIM + h0 + hl] = sq;
    } else {
        int i = (b - WT_BLOCKS) * 256 + tid;
        float4 v = g[i];
        __nv_bfloat162* o = reinterpret_cast<__nv_bfloat162*>(d_gb) + (size_t)i * 2;
        o[0] = __floats2bfloat162_rn(v.x, v.y);
        o[1] = __floats2bfloat162_rn(v.z, v.w);
    }
}

// finalize: inv = rsqrt(sum of 128 partials)
__global__ void norm_finalize_kernel() {
    int h = blockIdx.x * blockDim.x + threadIdx.x;
    float s = 0.f;
#pragma unroll 8
    for (int p = 0; p < KSLICES; ++p) s += d_norm_part[(size_t)p * N_DIM + h];
    d_norm_inv[h] = rsqrtf(s);
}

// --------------------- fused GEMM + partial LSE (R12 shape) ---------------------
// 256 threads = 8 warps in 4(M) x 2(N); each warp computes 32x64. 2 CTAs/SM.
// W is unnormalized in the GEMM; per-column 1/||W_col|| applied in epilogue.

__global__ void __launch_bounds__(THREADS, 2) gemm_lse_kernel() {
    extern __shared__ char smem[];
    const uint32_t sb = smem_u32(smem);
    const int tid = threadIdx.x;
    const int wid = tid >> 5;
    const int lane = tid & 31;
    const int mw = wid & 3;        // warp M index (0..3)
    const int nw = wid >> 2;       // warp N index (0..1)
    const int m0 = blockIdx.x * TILE_M;    // x = m tile (wave shares B band)
    const int n0 = blockIdx.y * TILE_N;

    const char* aBase = (const char*)d_gb + (size_t)m0 * (K_DIM * 2);
    const char* bBase = (const char*)d_wt + (size_t)n0 * (K_DIM * 2);

    auto load_stage = [&](int s, int it) {
        const uint32_t ab = sb + s * STAGE_BYTES;
        const uint32_t bb = ab + A_STAGE;
        const char* aK = aBase + it * (TILE_K * 2);
        const char* bK = bBase + it * (TILE_K * 2);
#pragma unroll
        for (int i = 0; i < A_STAGE / 16 / THREADS; ++i) {        // 4
            int idx = tid + i * THREADS;
            cp_async16(ab + swz((uint32_t)idx * 16),
                       aK + (size_t)(idx >> 3) * (K_DIM * 2) + (idx & 7) * 16);
        }
#pragma unroll
        for (int i = 0; i < B_STAGE / 16 / THREADS; ++i) {        // 4
            int idx = tid + i * THREADS;
            cp_async16(bb + swz((uint32_t)idx * 16),
                       bK + (size_t)(idx >> 3) * (K_DIM * 2) + (idx & 7) * 16);
        }
    };

    load_stage(0, 0); cp_commit();
    load_stage(1, 1); cp_commit();

    float acc[2][8][4];
#pragma unroll
    for (int t = 0; t < 2; ++t)
#pragma unroll
        for (int j = 0; j < 8; ++j)
#pragma unroll
            for (int c = 0; c < 4; ++c) acc[t][j][c] = 0.f;

    // ---- precomputed swizzled LDSM offsets; k-chunk applied via XOR ----
    const int a_row = lane & 15;
    const int a_kh  = lane >> 4;
    const int b_row = lane & 7;
    const int b_grp = (lane >> 3) & 1;
    const int b_t2  = lane >> 4;
    uint32_t a_off[2], b_off[4];
#pragma unroll
    for (int t = 0; t < 2; ++t)
        a_off[t] = swz((uint32_t)(mw * 32 + t * 16 + a_row) * 128 + a_kh * 16);
#pragma unroll
    for (int p = 0; p < 4; ++p)
        b_off[p] = swz((uint32_t)(nw * 64 + p * 16 + b_t2 * 8 + b_row) * 128 + b_grp * 16);

    for (int it = 0; it < K_ITERS; ++it) {
        cp_wait1();                 // stage `it` complete
        __syncthreads();
        if (it + 2 < K_ITERS) load_stage((it + 2) % STAGES, it + 2);
        cp_commit();

        const uint32_t stageA = sb + (it % STAGES) * STAGE_BYTES;
        const uint32_t stageB = stageA + A_STAGE;

#pragma unroll
        for (int ks = 0; ks < TILE_K / 16; ++ks) {    // 4 k16 steps
            const uint32_t kx = (uint32_t)(ks * 32);
            uint32_t a[2][4];
#pragma unroll
            for (int t = 0; t < 2; ++t)
                ldsm_x4(a[t][0], a[t][1], a[t][2], a[t][3], stageA + (a_off[t] ^ kx));
            uint32_t b[8][2];
#pragma unroll
            for (int p = 0; p < 4; ++p) {
                uint32_t r0, r1, r2, r3;
                ldsm_x4(r0, r1, r2, r3, stageB + (b_off[p] ^ kx));
                b[p * 2][0] = r0; b[p * 2][1] = r1;
                b[p * 2 + 1][0] = r2; b[p * 2 + 1][1] = r3;
            }
#pragma unroll
            for (int t = 0; t < 2; ++t)
#pragma unroll
                for (int j = 0; j < 8; ++j)
                    mma_bf16(acc[t][j][0], acc[t][j][1], acc[t][j][2], acc[t][j][3],
                             a[t][0], a[t][1], a[t][2], a[t][3], b[j][0], b[j][1]);
        }
    }

    // ---- apply column normalization to accumulators (fp32) ----
    float ninv[8][2];
#pragma unroll
    for (int j = 0; j < 8; ++j) {
        int n = n0 + nw * 64 + j * 8 + (lane & 3) * 2;
        ninv[j][0] = d_norm_inv[n];
        ninv[j][1] = d_norm_inv[n + 1];
    }
#pragma unroll
    for (int t = 0; t < 2; ++t)
#pragma unroll
        for (int j = 0; j < 8; ++j) {
            acc[t][j][0] *= ninv[j][0];
            acc[t][j][1] *= ninv[j][1];
            acc[t][j][2] *= ninv[j][0];
            acc[t][j][3] *= ninv[j][1];
        }

    __syncthreads();   // all warps done; reuse stage smem for reduction

    // ---- fused epilogue: per-row partial logsumexp over this tile's 128 cols ----
    float2* red = (float2*)smem;   // [2 n-warps][128 rows]
#pragma unroll
    for (int t = 0; t < 2; ++t) {
#pragma unroll
        for (int half = 0; half < 2; ++half) {
            float mx = -3.4e38f;
#pragma unroll
            for (int j = 0; j < 8; ++j) {
                mx = fmaxf(mx, acc[t][j][half * 2]);
                mx = fmaxf(mx, acc[t][j][half * 2 + 1]);
            }
            mx = fmaxf(mx, __shfl_xor_sync(0xFFFFFFFF, mx, 1));
            mx = fmaxf(mx, __shfl_xor_sync(0xFFFFFFFF, mx, 2));
            float s = 0.f;
#pragma unroll
            for (int j = 0; j < 8; ++j) {
                s += __expf(acc[t][j][half * 2] - mx);
                s += __expf(acc[t][j][half * 2 + 1] - mx);
            }
            s += __shfl_xor_sync(0xFFFFFFFF, s, 1);
            s += __shfl_xor_sync(0xFFFFFFFF, s, 2);
            if ((lane & 3) == 0) {
                int row = mw * 32 + t * 16 + half * 8 + (lane >> 2);
                red[nw * 128 + row] = make_float2(mx, s);
            }
        }
    }
    __syncthreads();

    if (tid < TILE_M) {
        float2 v0 = red[tid], v1 = red[128 + tid];
        float m = fmaxf(v0.x, v1.x);
        float s = v0.y * __expf(v0.x - m) + v1.y * __expf(v1.x - m);
        d_partial[(size_t)blockIdx.y * M_TOTAL + m0 + tid] = m + __logf(s);
    }
}

// --------------------- two-stage final LSE combine ---------------------
// stage 1: grid (32, JSPLIT); each block reduces 32 of 128 n_tiles for 256 rows
__global__ void reduce1_kernel() {
    int m = blockIdx.x * blockDim.x + threadIdx.x;
    int js = blockIdx.y;
    int j0 = js * (N_TILES / JSPLIT);
    float mx = -3.4e38f;
#pragma unroll 8
    for (int j = j0; j < j0 + N_TILES / JSPLIT; ++j)
        mx = fmaxf(mx, d_partial[(size_t)j * M_TOTAL + m]);
    float s = 0.f;
#pragma unroll 8
    for (int j = j0; j < j0 + N_TILES / JSPLIT; ++j)
        s += __expf(d_partial[(size_t)j * M_TOTAL + m] - mx);
    d_partial2[(size_t)js * M_TOTAL + m] = make_float2(mx, s);
}

// stage 2: combine JSPLIT (max, sum) pairs per row
__global__ void reduce2_kernel(float* __restrict__ out) {
    int m = blockIdx.x * blockDim.x + threadIdx.x;
    float mx = -3.4e38f;
#pragma unroll
    for (int p = 0; p < JSPLIT; ++p)
        mx = fmaxf(mx, d_partial2[(size_t)p * M_TOTAL + m].x);
    float s = 0.f;
#pragma unroll
    for (int p = 0; p < JSPLIT; ++p) {
        float2 v = d_partial2[(size_t)p * M_TOTAL + m];
        s += v.y * __expf(v.x - mx);
    }
    out[m] = mx + logf(s);
}

// --------------------- launcher ---------------------
extern "C" void kernel_launch(void* const* d_in, const int* in_sizes, int n_in,
                              void* d_out, int out_size) {
    const float* g;
    const float* W;
    if (in_sizes[0] == M_TOTAL * K_DIM) {           // g first (expected metadata order)
        g = (const float*)d_in[0];
        W = (const float*)d_in[1];
    } else {
        g = (const float*)d_in[1];
        W = (const float*)d_in[0];
    }
    float* out = (float*)d_out;

    prep_kernel<<<WT_BLOCKS + GB_BLOCKS, 256>>>(W, (const float4*)g);
    norm_finalize_kernel<<<N_DIM / 256, 256>>>();

    cudaFuncSetAttribute(gemm_lse_kernel, cudaFuncAttributeMaxDynamicSharedMemorySize,
                         SMEM_TOTAL_GEMM);
    gemm_lse_kernel<<<dim3(M_TILES, N_TILES), THREADS, SMEM_TOTAL_GEMM>>>();

    reduce1_kernel<<<dim3(M_TOTAL / 256, JSPLIT), 256>>>();
    reduce2_kernel<<<M_TOTAL / 256, 256>>>(out);
}

// round 15
// speedup vs baseline: 1.1001x; 1.0394x over previous
#include <cuda_runtime.h>
#include <cuda_bf16.h>
#include <cstdint>
#include <cstddef>

// Problem dims (fixed by the dataset)
#define M_TOTAL 8192
#define K_DIM   4096
#define N_DIM   16384
#define TILE_M  128
#define TILE_N  128
#define TILE_K  64
#define K_ITERS (K_DIM / TILE_K)   // 64
#define N_TILES (N_DIM / TILE_N)   // 128
#define M_TILES (M_TOTAL / TILE_M) // 64
#define THREADS 256                // 8 warps: 4(M) x 2(N), 32x64 per warp
#define STAGES  3
#define KSLICES (K_DIM / 64)       // 64 norm partials (one per 64-row k slice)
#define JSPLIT  8                  // reduce parallelism over n_tiles

#define A_STAGE (TILE_M * TILE_K * 2)            // 16384 B
#define B_STAGE (TILE_N * TILE_K * 2)            // 16384 B
#define STAGE_BYTES (A_STAGE + B_STAGE)          // 32768
#define SMEM_TOTAL_GEMM (STAGES * STAGE_BYTES)   // 98304 (x2 CTAs = 192K/SM)

#define WT_BLOCKS ((N_DIM / 32) * (K_DIM / 64))  // 32768
#define GB_BLOCKS ((M_TOTAL * K_DIM / 4) / 256)  // 32768

// -------- static device scratch (no allocations allowed) --------
__device__ float          d_norm_part[(size_t)KSLICES * N_DIM];   // per-k-slice col sq-sums
__device__ float          d_norm_inv[N_DIM];
__device__ __nv_bfloat16  d_gb[(size_t)M_TOTAL * K_DIM];          // g in bf16, [M,K] row-major
__device__ __nv_bfloat16  d_wt[(size_t)N_DIM * K_DIM];            // W^T bf16 (UNnormalized), [N,K]
__device__ float          d_partial[(size_t)N_TILES * M_TOTAL];   // partial LSE [n_tile][m]
__device__ float2         d_partial2[(size_t)JSPLIT * M_TOTAL];   // stage-2 (max, sum) pairs

// ------------------------- PTX helpers -------------------------
__device__ __forceinline__ uint32_t smem_u32(const void* p) {
    return (uint32_t)__cvta_generic_to_shared(p);
}
__device__ __forceinline__ void cp_async16(uint32_t smem, const void* gmem) {
    asm volatile("cp.async.cg.shared.global [%0], [%1], 16;" :: "r"(smem), "l"(gmem));
}
__device__ __forceinline__ void cp_commit() {
    asm volatile("cp.async.commit_group;" ::: "memory");
}
__device__ __forceinline__ void cp_wait1() {
    asm volatile("cp.async.wait_group 1;" ::: "memory");
}
__device__ __forceinline__ void ldsm_x4(uint32_t& r0, uint32_t& r1, uint32_t& r2, uint32_t& r3,
                                        uint32_t addr) {
    asm volatile("ldmatrix.sync.aligned.m8n8.x4.shared.b16 {%0,%1,%2,%3}, [%4];"
                 : "=r"(r0), "=r"(r1), "=r"(r2), "=r"(r3) : "r"(addr));
}
__device__ __forceinline__ void mma_bf16(float& d0, float& d1, float& d2, float& d3,
                                         uint32_t a0, uint32_t a1, uint32_t a2, uint32_t a3,
                                         uint32_t b0, uint32_t b1) {
    asm volatile(
        "mma.sync.aligned.m16n8k16.row.col.f32.bf16.bf16.f32 "
        "{%0,%1,%2,%3}, {%4,%5,%6,%7}, {%8,%9}, {%0,%1,%2,%3};"
        : "+f"(d0), "+f"(d1), "+f"(d2), "+f"(d3)
        : "r"(a0), "r"(a1), "r"(a2), "r"(a3), "r"(b0), "r"(b1));
}
__device__ __forceinline__ uint32_t swz(uint32_t byte_off) {
    return byte_off ^ ((byte_off >> 3) & 0x70);
}

// --------------------- merged prep kernel ---------------------
// Blocks [0, WT_BLOCKS): transpose W -> bf16 (unnormalized, 64k x 32h tiles,
// 16B vector stores) + per-64k-slice column sq-sums.
// Blocks [WT_BLOCKS, ...): g -> bf16. Both DRAM-bound; merged to overlap.
__global__ void prep_kernel(const float* __restrict__ W, const float4* __restrict__ g) {
    __shared__ float tile[64][33];     // [k_local][h_local] (wt path only)
    const int b = blockIdx.x;
    const int tid = threadIdx.x;

    if (b < WT_BLOCKS) {
        const int h0 = (b & (N_DIM / 32 - 1)) * 32;
        const int kb = b >> 9;                       // 64-k slice index (N_DIM/32 = 512)
        const int k0 = kb * 64;
        const int tx = tid & 31, ty = tid >> 5;      // (32, 8)
#pragma unroll
        for (int j = 0; j < 64; j += 8)
            tile[ty + j][tx] = W[(size_t)(k0 + ty + j) * N_DIM + h0 + tx];
        __syncthreads();
        // thread -> (h row, 8-k chunk): one 16B store of 8 bf16
        const int hl = tid >> 3;                     // 0..31
        const int kc = tid & 7;                      // 0..7
        const int h = h0 + hl;
        __nv_bfloat162 pk[4];
        float sq = 0.f;
#pragma unroll
        for (int i = 0; i < 4; ++i) {
            float v0 = tile[kc * 8 + i * 2 + 0][hl];
            float v1 = tile[kc * 8 + i * 2 + 1][hl];
            pk[i] = __floats2bfloat162_rn(v0, v1);
            sq = fmaf(v0, v0, sq);
            sq = fmaf(v1, v1, sq);
        }
        *reinterpret_cast<uint4*>(d_wt + (size_t)h * K_DIM + k0 + kc * 8) =
            *reinterpret_cast<uint4*>(pk);
        sq += __shfl_down_sync(0xFFFFFFFF, sq, 4);
        sq += __shfl_down_sync(0xFFFFFFFF, sq, 2);
        sq += __shfl_down_sync(0xFFFFFFFF, sq, 1);
        if (kc == 0)
            d_norm_part[(size_t)kb * N_DIM + h] = sq;
    } else {
        int i = (b - WT_BLOCKS) * 256 + tid;
        float4 v = g[i];
        __nv_bfloat162* o = reinterpret_cast<__nv_bfloat162*>(d_gb) + (size_t)i * 2;
        o[0] = __floats2bfloat162_rn(v.x, v.y);
        o[1] = __floats2bfloat162_rn(v.z, v.w);
    }
}

// finalize: inv = rsqrt(sum of KSLICES partials)
__global__ void norm_finalize_kernel() {
    int h = blockIdx.x * blockDim.x + threadIdx.x;
    float s = 0.f;
#pragma unroll 8
    for (int p = 0; p < KSLICES; ++p) s += d_norm_part[(size_t)p * N_DIM + h];
    d_norm_inv[h] = rsqrtf(s);
}

// --------------------- fused GEMM + partial LSE ---------------------
// 256 threads = 8 warps in 4(M) x 2(N); each warp computes 32x64. 2 CTAs/SM.
// Iteration order: wait -> sync -> LDSM/MMA -> issue loads(it+2) -> commit.
// Issuing loads AFTER compute lets the tensor pipe refill immediately
// post-barrier; the cp.async issue burst overlaps the MMA drain instead of
// delaying the first ldmatrix. Slot-reuse guard unchanged (sync at iter it
// covers last readers of slot (it+2)%3, which ran at iter it-1).

__global__ void __launch_bounds__(THREADS, 2) gemm_lse_kernel() {
    extern __shared__ char smem[];
    const uint32_t sb = smem_u32(smem);
    const int tid = threadIdx.x;
    const int wid = tid >> 5;
    const int lane = tid & 31;
    const int mw = wid & 3;        // warp M index (0..3)
    const int nw = wid >> 2;       // warp N index (0..1)
    const int m0 = blockIdx.x * TILE_M;    // x = m tile (wave shares B band)
    const int n0 = blockIdx.y * TILE_N;

    const char* aBase = (const char*)d_gb + (size_t)m0 * (K_DIM * 2);
    const char* bBase = (const char*)d_wt + (size_t)n0 * (K_DIM * 2);

    auto load_stage = [&](int s, int it) {
        const uint32_t ab = sb + s * STAGE_BYTES;
        const uint32_t bb = ab + A_STAGE;
        const char* aK = aBase + it * (TILE_K * 2);
        const char* bK = bBase + it * (TILE_K * 2);
#pragma unroll
        for (int i = 0; i < A_STAGE / 16 / THREADS; ++i) {        // 4
            int idx = tid + i * THREADS;
            cp_async16(ab + swz((uint32_t)idx * 16),
                       aK + (size_t)(idx >> 3) * (K_DIM * 2) + (idx & 7) * 16);
        }
#pragma unroll
        for (int i = 0; i < B_STAGE / 16 / THREADS; ++i) {        // 4
            int idx = tid + i * THREADS;
            cp_async16(bb + swz((uint32_t)idx * 16),
                       bK + (size_t)(idx >> 3) * (K_DIM * 2) + (idx & 7) * 16);
        }
    };

    load_stage(0, 0); cp_commit();
    load_stage(1, 1); cp_commit();

    float acc[2][8][4];
#pragma unroll
    for (int t = 0; t < 2; ++t)
#pragma unroll
        for (int j = 0; j < 8; ++j)
#pragma unroll
            for (int c = 0; c < 4; ++c) acc[t][j][c] = 0.f;

    // ---- precomputed swizzled LDSM offsets; k-chunk applied via XOR ----
    const int a_row = lane & 15;
    const int a_kh  = lane >> 4;
    const int b_row = lane & 7;
    const int b_grp = (lane >> 3) & 1;
    const int b_t2  = lane >> 4;
    uint32_t a_off[2], b_off[4];
#pragma unroll
    for (int t = 0; t < 2; ++t)
        a_off[t] = swz((uint32_t)(mw * 32 + t * 16 + a_row) * 128 + a_kh * 16);
#pragma unroll
    for (int p = 0; p < 4; ++p)
        b_off[p] = swz((uint32_t)(nw * 64 + p * 16 + b_t2 * 8 + b_row) * 128 + b_grp * 16);

    for (int it = 0; it < K_ITERS; ++it) {
        cp_wait1();                 // stage `it` complete
        __syncthreads();

        const uint32_t stageA = sb + (it % STAGES) * STAGE_BYTES;
        const uint32_t stageB = stageA + A_STAGE;

#pragma unroll
        for (int ks = 0; ks < TILE_K / 16; ++ks) {    // 4 k16 steps
            const uint32_t kx = (uint32_t)(ks * 32);
            uint32_t a[2][4];
#pragma unroll
            for (int t = 0; t < 2; ++t)
                ldsm_x4(a[t][0], a[t][1], a[t][2], a[t][3], stageA + (a_off[t] ^ kx));
            uint32_t b[8][2];
#pragma unroll
            for (int p = 0; p < 4; ++p) {
                uint32_t r0, r1, r2, r3;
                ldsm_x4(r0, r1, r2, r3, stageB + (b_off[p] ^ kx));
                b[p * 2][0] = r0; b[p * 2][1] = r1;
                b[p * 2 + 1][0] = r2; b[p * 2 + 1][1] = r3;
            }
#pragma unroll
            for (int t = 0; t < 2; ++t)
#pragma unroll
                for (int j = 0; j < 8; ++j)
                    mma_bf16(acc[t][j][0], acc[t][j][1], acc[t][j][2], acc[t][j][3],
                             a[t][0], a[t][1], a[t][2], a[t][3], b[j][0], b[j][1]);
        }

        if (it + 2 < K_ITERS) load_stage((it + 2) % STAGES, it + 2);
        cp_commit();                // commit every iter keeps wait_group uniform
    }

    // ---- apply column normalization to accumulators (fp32) ----
    float ninv[8][2];
#pragma unroll
    for (int j = 0; j < 8; ++j) {
        int n = n0 + nw * 64 + j * 8 + (lane & 3) * 2;
        ninv[j][0] = d_norm_inv[n];
        ninv[j][1] = d_norm_inv[n + 1];
    }
#pragma unroll
    for (int t = 0; t < 2; ++t)
#pragma unroll
        for (int j = 0; j < 8; ++j) {
            acc[t][j][0] *= ninv[j][0];
            acc[t][j][1] *= ninv[j][1];
            acc[t][j][2] *= ninv[j][0];
            acc[t][j][3] *= ninv[j][1];
        }

    __syncthreads();   // all warps done; reuse stage smem for reduction

    // ---- fused epilogue: per-row partial logsumexp over this tile's 128 cols ----
    float2* red = (float2*)smem;   // [2 n-warps][128 rows]
#pragma unroll
    for (int t = 0; t < 2; ++t) {
#pragma unroll
        for (int half = 0; half < 2; ++half) {
            float mx = -3.4e38f;
#pragma unroll
            for (int j = 0; j < 8; ++j) {
                mx = fmaxf(mx, acc[t][j][half * 2]);
                mx = fmaxf(mx, acc[t][j][half * 2 + 1]);
            }
            mx = fmaxf(mx, __shfl_xor_sync(0xFFFFFFFF, mx, 1));
            mx = fmaxf(mx, __shfl_xor_sync(0xFFFFFFFF, mx, 2));
            float s = 0.f;
#pragma unroll
            for (int j = 0; j < 8; ++j) {
                s += __expf(acc[t][j][half * 2] - mx);
                s += __expf(acc[t][j][half * 2 + 1] - mx);
            }
            s += __shfl_xor_sync(0xFFFFFFFF, s, 1);
            s += __shfl_xor_sync(0xFFFFFFFF, s, 2);
            if ((lane & 3) == 0) {
                int row = mw * 32 + t * 16 + half * 8 + (lane >> 2);
                red[nw * 128 + row] = make_float2(mx, s);
            }
        }
    }
    __syncthreads();

    if (tid < TILE_M) {
        float2 v0 = red[tid], v1 = red[128 + tid];
        float m = fmaxf(v0.x, v1.x);
        float s = v0.y * __expf(v0.x - m) + v1.y * __expf(v1.x - m);
        d_partial[(size_t)blockIdx.y * M_TOTAL + m0 + tid] = m + __logf(s);
    }
}

// --------------------- two-stage final LSE combine ---------------------
__global__ void reduce1_kernel() {
    int m = blockIdx.x * blockDim.x + threadIdx.x;
    int js = blockIdx.y;
    int j0 = js * (N_TILES / JSPLIT);
    float mx = -3.4e38f;
#pragma unroll 8
    for (int j = j0; j < j0 + N_TILES / JSPLIT; ++j)
        mx = fmaxf(mx, d_partial[(size_t)j * M_TOTAL + m]);
    float s = 0.f;
#pragma unroll 8
    for (int j = j0; j < j0 + N_TILES / JSPLIT; ++j)
        s += __expf(d_partial[(size_t)j * M_TOTAL + m] - mx);
    d_partial2[(size_t)js * M_TOTAL + m] = make_float2(mx, s);
}

__global__ void reduce2_kernel(float* __restrict__ out) {
    int m = blockIdx.x * blockDim.x + threadIdx.x;
    float mx = -3.4e38f;
#pragma unroll
    for (int p = 0; p < JSPLIT; ++p)
        mx = fmaxf(mx, d_partial2[(size_t)p * M_TOTAL + m].x);
    float s = 0.f;
#pragma unroll
    for (int p = 0; p < JSPLIT; ++p) {
        float2 v = d_partial2[(size_t)p * M_TOTAL + m];
        s += v.y * __expf(v.x - mx);
    }
    out[m] = mx + logf(s);
}

// --------------------- launcher ---------------------
extern "C" void kernel_launch(void* const* d_in, const int* in_sizes, int n_in,
                              void* d_out, int out_size) {
    const float* g;
    const float* W;
    if (in_sizes[0] == M_TOTAL * K_DIM) {           // g first (expected metadata order)
        g = (const float*)d_in[0];
        W = (const float*)d_in[1];
    } else {
        g = (const float*)d_in[1];
        W = (const float*)d_in[0];
    }
    float* out = (float*)d_out;

    prep_kernel<<<WT_BLOCKS + GB_BLOCKS, 256>>>(W, (const float4*)g);
    norm_finalize_kernel<<<N_DIM / 256, 256>>>();

    cudaFuncSetAttribute(gemm_lse_kernel, cudaFuncAttributeMaxDynamicSharedMemorySize,
                         SMEM_TOTAL_GEMM);
    gemm_lse_kernel<<<dim3(M_TILES, N_TILES), THREADS, SMEM_TOTAL_GEMM>>>();

    reduce1_kernel<<<dim3(M_TOTAL / 256, JSPLIT), 256>>>();
    reduce2_kernel<<<M_TOTAL / 256, 256>>>(out);
}